// round 10
// baseline (speedup 1.0000x reference)
#include <cuda_runtime.h>

// LinearInverse_45664092291621
//
// Reference returns y + score(y) = y - y = 0 exactly (score(x) = -x):
// output is zeros((1048576, 2), float32) = 8 MB of zeros.
//
// Established: every single-node 8 MB fill (STG kernels, TMA bulk store,
// driver memset) costs ~4.5-5 us GPU time ~= fixed per-kernel overhead
// (~2.7 us) + L2-resident store traffic (~1.5-2 us). Single memset node
// replays at 6.176 us total (measured twice, bit-identical).
//
// R9 was an infra failure (container never ran) -- resubmitting unchanged.
//
// Fork-join graph with TWO parallel memset branches of 4 MB each: the fixed
// kernel overheads overlap, so ideal GPU time is max-of-branches
// (~2.7 + 0.9 us) instead of the serial 4.5 us. The side stream + events are
// created on the first call (the correctness run, outside capture); during
// capture only memsets + event edges are recorded. Identical GPU work every
// call; no device-memory allocation.

static cudaStream_t g_s1 = nullptr;
static cudaEvent_t g_fork = nullptr;
static cudaEvent_t g_join = nullptr;

extern "C" void kernel_launch(void* const* d_in, const int* in_sizes, int n_in,
                              void* d_out, int out_size) {
    (void)d_in; (void)in_sizes; (void)n_in;

    if (g_s1 == nullptr) {
        cudaStreamCreateWithFlags(&g_s1, cudaStreamNonBlocking);
        cudaEventCreateWithFlags(&g_fork, cudaEventDisableTiming);
        cudaEventCreateWithFlags(&g_join, cudaEventDisableTiming);
    }

    size_t total = (size_t)out_size * sizeof(float);
    size_t half = (total / 2) & ~(size_t)255;   // 256B-aligned split
    char* base = (char*)d_out;

    if (half == 0) {
        // Degenerate tiny output: single memset.
        cudaMemsetAsync(base, 0, total, 0);
        return;
    }

    // Fork: branch B (stream g_s1) depends on the capture point.
    cudaEventRecord(g_fork, 0);
    cudaStreamWaitEvent(g_s1, g_fork, 0);

    // Branch A on the main (captured) stream, branch B on the side stream.
    cudaMemsetAsync(base, 0, half, 0);
    cudaMemsetAsync(base + half, 0, total - half, g_s1);

    // Join: main stream waits for branch B.
    cudaEventRecord(g_join, g_s1);
    cudaStreamWaitEvent(0, g_join, 0);
}

// round 11
// speedup vs baseline: 1.3385x; 1.3385x over previous
#include <cuda_runtime.h>

// LinearInverse_45664092291621 — FINAL
//
// Reference analysis: score(x) = -x, and the function returns
// y + score(y) = y - y = 0 exactly, for every finite y. The 199-step
// Langevin scan, Threefry noise, and convergence logic are all dead code
// w.r.t. the output: the result is exactly zeros((1048576, 2), float32).
//
// Optimization search (all measured on the brokered Blackwell chip):
//   - STG zero-fill kernels, thin (2048 blk) and fat (512 blk) grids:
//       fill 4.7-4.8 us, totals 6.37-6.75 us
//   - TMA bulk-store (cp.async.bulk SMEM->GMEM): fill 5.09 us, total 6.85 us
//   - fork-join graph, 2 parallel memset nodes: total 8.22 us (regression)
//   - single driver memset node: total 6.176 us, bit-identical across runs
// Conclusion: every 8 MB fill pays ~the same fixed kernel overhead + the
// same L2-resident store traffic; the minimum-node graph (one memset node)
// is the floor. Graph parallelism and alternate write paths only add cost.
//
// cudaMemsetAsync on the capture stream records a single graph memset node:
// graph-capturable, allocation-free, deterministic. Zeros are bytewise zero,
// so one byte-memset of the whole float32 buffer is exact for any out_size.

extern "C" void kernel_launch(void* const* d_in, const int* in_sizes, int n_in,
                              void* d_out, int out_size) {
    (void)d_in; (void)in_sizes; (void)n_in;
    cudaMemsetAsync(d_out, 0, (size_t)out_size * sizeof(float), 0);
}